// round 11
// baseline (speedup 1.0000x reference)
#include <cuda_runtime.h>
#include <cstdint>

// ---------------- problem constants ----------------
#define BB   16
#define TT   34
#define TP   32          // T - DIL
#define NN   1000
#define CIN  32
#define DC   32
#define OC   64
#define EE   16000
#define NNZ  (EE + NN)   // edges + self loops = 17000
#define GG   (BB * TP)   // 512 graphs
#define NB   4           // nodes per k_gate block

#define OUT1_ELEMS ((size_t)BB * DC * NN * TP)        // 16,384,000

typedef unsigned long long u64c;

// ---------------- f32x2 packed helpers ----------------
__device__ __forceinline__ u64c fma2(u64c a, u64c b, u64c c) {
    u64c d;
    asm("fma.rn.f32x2 %0, %1, %2, %3;" : "=l"(d) : "l"(a), "l"(b), "l"(c));
    return d;
}
__device__ __forceinline__ u64c add2(u64c a, u64c b) {
    u64c d;
    asm("add.rn.f32x2 %0, %1, %2;" : "=l"(d) : "l"(a), "l"(b));
    return d;
}
__device__ __forceinline__ float f2sum(u64c a) {
    return __int_as_float((int)(a & 0xffffffffULL)) +
           __int_as_float((int)(a >> 32));
}
__device__ __forceinline__ u64c pack2(float lo, float hi) {
    u64c r;
    asm("mov.b64 %0, {%1, %2};" : "=l"(r) : "f"(lo), "f"(hi));
    return r;
}
__device__ __forceinline__ float u64lo(u64c a) { return __int_as_float((int)(a & 0xffffffffULL)); }
__device__ __forceinline__ float u64hi(u64c a) { return __int_as_float((int)(a >> 32)); }

// ---------------- device scratch ----------------
__device__ float g_z[(size_t)GG * NN * OC];   // 131 MB: z = gated @ Wcomb^T
__device__ float g_wcomb[OC * DC];            // Wcomb[o][d] = sum_c wout[o][c] wgcn[c][d]
__device__ float g_ybias[OC];                 // bgcn @ wout^T + bout
__device__ int   g_off[NN + 1];
__device__ int2  g_csr[NNZ];                  // (src*128 byte offset, f32 val as int)

// ---------------- K_comb: combined weights (propagate/conv commute) --------
__global__ void k_comb(const float* __restrict__ wgcn, const float* __restrict__ bgcn,
                       const float* __restrict__ wout, const float* __restrict__ bout) {
    __shared__ float sg[CIN * DC];   // wgcn [c][d]
    __shared__ float so[OC * CIN];   // wout [o][c]
    __shared__ float sb[CIN];
    int tid = threadIdx.x;
    for (int f = tid; f < CIN * DC; f += blockDim.x) sg[f] = wgcn[f];
    for (int f = tid; f < OC * CIN; f += blockDim.x) so[f] = wout[f];
    if (tid < CIN) sb[tid] = bgcn[tid];
    __syncthreads();
    for (int f = tid; f < OC * DC; f += blockDim.x) {
        int o = f >> 5, d = f & 31;
        float s = 0.f;
#pragma unroll
        for (int c = 0; c < CIN; c++) s += so[o * CIN + c] * sg[c * DC + d];
        g_wcomb[f] = s;
    }
    if (tid < OC) {
        float s = bout[tid];
#pragma unroll
        for (int c = 0; c < CIN; c++) s += sb[c] * so[tid * CIN + c];
        g_ybias[tid] = s;
    }
}

// ---------------- K_build: fused CSR build (single block, smem atomics) ----
__global__ __launch_bounds__(1024) void k_build(const int* __restrict__ ei,
                                                const float* __restrict__ ew) {
    __shared__ float sdeg[NN];
    __shared__ int   scnt[NN];
    __shared__ int   ssc[1024];
    __shared__ int   scur[NN];
    int tid = threadIdx.x;

    for (int i = tid; i < NN; i += 1024) { sdeg[i] = 0.f; scnt[i] = 0; }
    __syncthreads();

    for (int i = tid; i < NNZ; i += 1024) {
        int d; float w;
        if (i < EE) { d = ei[EE + i]; w = ew[i]; }
        else        { d = i - EE;     w = 1.f;   }
        atomicAdd(&sdeg[d], w);
        atomicAdd(&scnt[d], 1);
    }
    __syncthreads();

    int v = (tid < NN) ? scnt[tid] : 0;
    ssc[tid] = v;
    __syncthreads();
    for (int off = 1; off < 1024; off <<= 1) {
        int tv = (tid >= off) ? ssc[tid - off] : 0;
        __syncthreads();
        ssc[tid] += tv;
        __syncthreads();
    }
    if (tid < NN) {
        int excl = ssc[tid] - v;
        scur[tid] = excl;
        g_off[tid] = excl;
    }
    if (tid == NN - 1) g_off[NN] = ssc[tid];
    __syncthreads();

    for (int i = tid; i < NNZ; i += 1024) {
        int s, d; float w;
        if (i < EE) { s = ei[i]; d = ei[EE + i]; w = ew[i]; }
        else        { s = i - EE; d = s;         w = 1.f;   }
        float degs = sdeg[s], degd = sdeg[d];
        float dis_s = (degs > 0.f) ? rsqrtf(degs) : 0.f;
        float dis_d = (degd > 0.f) ? rsqrtf(degd) : 0.f;
        int p = atomicAdd(&scur[d], 1);
        g_csr[p] = make_int2(s * 128, __float_as_int(dis_s * w * dis_d));
    }
}

// ---------------- K_gate: fused gated conv + z, NB=4 nodes per block -------
// Phase 1 (unchanged): warp wy owns o-quad, t = lane, NB-node weight reuse,
// packed fma2. Phase 2 (REMAPPED): warp wy owns o-OCTET {8wy..8wy+7}, lanes=t.
// gs reads become lane-strided LDS.128 (conflict-free, full crossbar rate,
// one read per (d4, nb) for all t). W float4s hoisted per d4 and packed into
// fma2 o-pair operands in registers. z staged in pitch-68 zbuf, then written
// out coalesced.
struct SmemGate {
    float4 xq[NB][8][34];                  // [nb][c4][t]
    float4 w1a[32][8], w1b[32][8];         // [o][c4]
    float4 w2a[32][8], w2b[32][8];
    float4 wcq[8][64];                     // [d4][o] = Wcomb[o][4d4..4d4+3]
    float  gs[NB][32 * 36];                // gated [t][d], pitch 36
    float  zbuf[NB][32 * 68];              // z [t][o], pitch 68
};

__global__ __launch_bounds__(256) void k_gate(
    const float* __restrict__ x,
    const float* __restrict__ wg1, const float* __restrict__ bg1,
    const float* __restrict__ wg2, const float* __restrict__ bg2,
    float* __restrict__ out1)
{
    extern __shared__ char smem_raw[];
    SmemGate& S = *(SmemGate*)smem_raw;

    int blk = blockIdx.x;                  // 4000 blocks
    int b  = blk / (NN / NB);
    int n0 = (blk - b * (NN / NB)) * NB;

    int tx = threadIdx.x;                  // 0..31 (t)
    int wy = threadIdx.y;                  // 0..7
    int tid = wy * 32 + tx;

    // stage gate weights (flat f = o*32+c, 1024 per array)
    for (int f = tid; f < 32 * 32; f += 256) {
        float2 v1 = *(const float2*)(wg1 + f * 2);
        float2 v2 = *(const float2*)(wg2 + f * 2);
        ((float*)S.w1a)[f] = v1.x;
        ((float*)S.w1b)[f] = v1.y;
        ((float*)S.w2a)[f] = v2.x;
        ((float*)S.w2b)[f] = v2.y;
    }
    // stage Wcomb: flat f = (d4*64+o)*4+k  <-  wcomb[o*32 + d4*4 + k]
    for (int f = tid; f < 8 * 64 * 4; f += 256) {
        int k = f & 3, o = (f >> 2) & 63, d4 = f >> 8;
        ((float*)S.wcq)[f] = g_wcomb[o * 32 + d4 * 4 + k];
    }
    // stage x tiles: NB nodes x 34 t x 8 c4
    for (int f = tid; f < NB * 34 * 8; f += 256) {
        int nb = f / (34 * 8);
        int r  = f - nb * (34 * 8);
        int t = r >> 3, c4 = r & 7;
        S.xq[nb][c4][t] =
            *(const float4*)(x + ((size_t)(b * TT + t) * NN + (n0 + nb)) * CIN + c4 * 4);
    }
    __syncthreads();

    // ---- phase 1: gates ----
    {
        float bg1v[4], bg2v[4];
#pragma unroll
        for (int oo = 0; oo < 4; oo++) {
            bg1v[oo] = __ldg(bg1 + 4 * wy + oo);
            bg2v[oo] = __ldg(bg2 + 4 * wy + oo);
        }
        u64c a1[4][NB], a2[4][NB];
#pragma unroll
        for (int oo = 0; oo < 4; oo++)
#pragma unroll
            for (int nb = 0; nb < NB; nb++) { a1[oo][nb] = 0; a2[oo][nb] = 0; }

#pragma unroll
        for (int c4 = 0; c4 < 8; c4++) {
            ulonglong2 xa[NB], xb[NB];
#pragma unroll
            for (int nb = 0; nb < NB; nb++) {
                xa[nb] = *(const ulonglong2*)&S.xq[nb][c4][tx];
                xb[nb] = *(const ulonglong2*)&S.xq[nb][c4][tx + 2];
            }
#pragma unroll
            for (int oo = 0; oo < 4; oo++) {
                int o = 4 * wy + oo;
                ulonglong2 A1 = *(const ulonglong2*)&S.w1a[o][c4];
                ulonglong2 B1 = *(const ulonglong2*)&S.w1b[o][c4];
                ulonglong2 A2 = *(const ulonglong2*)&S.w2a[o][c4];
                ulonglong2 B2 = *(const ulonglong2*)&S.w2b[o][c4];
#pragma unroll
                for (int nb = 0; nb < NB; nb++) {
                    a1[oo][nb] = fma2(xa[nb].x, A1.x, a1[oo][nb]);
                    a1[oo][nb] = fma2(xa[nb].y, A1.y, a1[oo][nb]);
                    a1[oo][nb] = fma2(xb[nb].x, B1.x, a1[oo][nb]);
                    a1[oo][nb] = fma2(xb[nb].y, B1.y, a1[oo][nb]);
                    a2[oo][nb] = fma2(xa[nb].x, A2.x, a2[oo][nb]);
                    a2[oo][nb] = fma2(xa[nb].y, A2.y, a2[oo][nb]);
                    a2[oo][nb] = fma2(xb[nb].x, B2.x, a2[oo][nb]);
                    a2[oo][nb] = fma2(xb[nb].y, B2.y, a2[oo][nb]);
                }
            }
        }

#pragma unroll
        for (int nb = 0; nb < NB; nb++) {
            float4 gq;
#pragma unroll
            for (int oo = 0; oo < 4; oo++) {
                int o = 4 * wy + oo;
                float s1 = f2sum(a1[oo][nb]) + bg1v[oo];
                float s2 = f2sum(a2[oo][nb]) + bg2v[oo];
                float e1 = __expf(2.f * s1);
                float th = 1.f - __fdividef(2.f, e1 + 1.f);    // tanh, inf-safe
                float sg = __fdividef(1.f, 1.f + __expf(-s2)); // sigmoid
                float gated = th * sg;
                out1[((size_t)(b * DC + o) * NN + (n0 + nb)) * TP + tx] = gated;
                (&gq.x)[oo] = gated;
            }
            *(float4*)&S.gs[nb][tx * 36 + 4 * wy] = gq;   // conflict-free STS.128
        }
    }
    __syncthreads();

    // ---- phase 2 (remapped): z[t][o-octet] with lanes = t ----
    {
        int o0 = wy * 8;
        u64c acc[NB][4];                    // [nb][o-pair], z for 8 o's
#pragma unroll
        for (int nb = 0; nb < NB; nb++)
#pragma unroll
            for (int p = 0; p < 4; p++) acc[nb][p] = 0;

#pragma unroll
        for (int d4 = 0; d4 < 8; d4++) {
            // hoisted W loads (warp-uniform broadcast), packed into o-pairs
            float4 wf[8];
#pragma unroll
            for (int j = 0; j < 8; j++) wf[j] = S.wcq[d4][o0 + j];
            u64c Wp[4][4];                  // [o-pair][d]
#pragma unroll
            for (int p = 0; p < 4; p++)
#pragma unroll
                for (int d = 0; d < 4; d++)
                    Wp[p][d] = pack2((&wf[2 * p].x)[d], (&wf[2 * p + 1].x)[d]);

#pragma unroll
            for (int nb = 0; nb < NB; nb++) {
                float4 g4 = *(const float4*)&S.gs[nb][tx * 36 + d4 * 4];  // lane-strided, CF
                u64c gd[4];
#pragma unroll
                for (int d = 0; d < 4; d++) {
                    float gv = (&g4.x)[d];
                    gd[d] = pack2(gv, gv);
                }
#pragma unroll
                for (int p = 0; p < 4; p++)
#pragma unroll
                    for (int d = 0; d < 4; d++)
                        acc[nb][p] = fma2(gd[d], Wp[p][d], acc[nb][p]);
            }
        }

        // store z into zbuf (pitch 68, lane-strided CF STS.128)
#pragma unroll
        for (int nb = 0; nb < NB; nb++) {
            float4 lo, hi;
            lo.x = u64lo(acc[nb][0]); lo.y = u64hi(acc[nb][0]);
            lo.z = u64lo(acc[nb][1]); lo.w = u64hi(acc[nb][1]);
            hi.x = u64lo(acc[nb][2]); hi.y = u64hi(acc[nb][2]);
            hi.z = u64lo(acc[nb][3]); hi.w = u64hi(acc[nb][3]);
            float* zp = &S.zbuf[nb][tx * 68 + o0];
            *(float4*)zp       = lo;
            *(float4*)(zp + 4) = hi;
        }
    }
    __syncthreads();

    // ---- z readout: coalesced STG, lane-consecutive LDS ----
    for (int f = tid; f < NB * 32 * 64; f += 256) {
        int o  = f & 63;
        int t  = (f >> 6) & 31;
        int nb = f >> 11;
        g_z[((size_t)(b * TP + t) * NN + (n0 + nb)) * OC + o] =
            S.zbuf[nb][t * 68 + o];
    }
}

// ---------------- K_spmm: pure gather  y[g,i,:] = sum_e val*z[src,:] + ybias
// 1024 blocks = (graph g, channel-half). z half-slab (128 KB) in dynamic SMEM.
// Warp = 4 subgroups x 8 lanes; subgroup walks one row. MLP-4: 4 CSR entries
// prefetched per iteration, dual independent fma2 accumulator pairs.
__global__ __launch_bounds__(1024, 1) void k_spmm(float* __restrict__ y)
{
    extern __shared__ float z_s[];            // [N][32]
    int bx = blockIdx.x;
    int g = bx >> 1, half = bx & 1;
    int tid = threadIdx.x;

    for (int f = tid; f < NN * 8; f += 1024) {
        int n = f >> 3, c4 = f & 7;
        ((float4*)z_s)[f] =
            *(const float4*)(g_z + ((size_t)g * NN + n) * OC + half * 32 + c4 * 4);
    }
    __syncthreads();

    int warp = tid >> 5;
    int lane = tid & 31;
    int sub  = lane >> 3;                     // 0..3 row subgroup
    int c4   = lane & 7;                      // float4 channel group in half
    float4 yb4 = *(const float4*)(g_ybias + half * 32 + c4 * 4);
    const char* zb = (const char*)z_s + c4 * 16;

    for (int i0 = warp * 4 + sub; i0 < NN + 3; i0 += 128) {
        bool valid = (i0 < NN);
        int r0 = 0, r1 = 0;
        if (valid) { r0 = g_off[i0]; r1 = g_off[i0 + 1]; }

        u64c aA = pack2(yb4.x, yb4.y), aB = 0;
        u64c bA = pack2(yb4.z, yb4.w), bB = 0;

        int e = r0;
        for (; e + 4 <= r1; e += 4) {
            int2 e0 = __ldg(&g_csr[e]);
            int2 e1 = __ldg(&g_csr[e + 1]);
            int2 e2 = __ldg(&g_csr[e + 2]);
            int2 e3 = __ldg(&g_csr[e + 3]);
            ulonglong2 z0 = *(const ulonglong2*)(zb + e0.x);
            ulonglong2 z1 = *(const ulonglong2*)(zb + e1.x);
            ulonglong2 z2 = *(const ulonglong2*)(zb + e2.x);
            ulonglong2 z3 = *(const ulonglong2*)(zb + e3.x);
            float v0f = __int_as_float(e0.y), v1f = __int_as_float(e1.y);
            float v2f = __int_as_float(e2.y), v3f = __int_as_float(e3.y);
            u64c v0 = pack2(v0f, v0f), v1 = pack2(v1f, v1f);
            u64c v2 = pack2(v2f, v2f), v3 = pack2(v3f, v3f);
            aA = fma2(z0.x, v0, aA); bA = fma2(z0.y, v0, bA);
            aB = fma2(z1.x, v1, aB); bB = fma2(z1.y, v1, bB);
            aA = fma2(z2.x, v2, aA); bA = fma2(z2.y, v2, bA);
            aB = fma2(z3.x, v3, aB); bB = fma2(z3.y, v3, bB);
        }
        for (; e < r1; e++) {
            int2 ev = __ldg(&g_csr[e]);
            float vf = __int_as_float(ev.y);
            u64c vv = pack2(vf, vf);
            ulonglong2 zz = *(const ulonglong2*)(zb + ev.x);
            aA = fma2(zz.x, vv, aA);
            bA = fma2(zz.y, vv, bA);
        }
        u64c a0 = add2(aA, aB);
        u64c b0 = add2(bA, bB);

        if (valid) {
            float4 r;
            r.x = u64lo(a0); r.y = u64hi(a0);
            r.z = u64lo(b0); r.w = u64hi(b0);
            *(float4*)(y + ((size_t)g * NN + i0) * OC + half * 32 + c4 * 4) = r;
        }
    }
}

// ---------------- launcher ----------------
extern "C" void kernel_launch(void* const* d_in, const int* in_sizes, int n_in,
                              void* d_out, int out_size)
{
    const float* x    = (const float*)d_in[0];
    const int*   ei   = (const int*)  d_in[1];
    const float* ew   = (const float*)d_in[2];
    const float* wg1  = (const float*)d_in[3];
    const float* bg1  = (const float*)d_in[4];
    const float* wg2  = (const float*)d_in[5];
    const float* bg2  = (const float*)d_in[6];
    const float* wgcn = (const float*)d_in[7];
    const float* bgcn = (const float*)d_in[8];
    const float* wout = (const float*)d_in[9];
    const float* bout = (const float*)d_in[10];
    float* out = (float*)d_out;

    // 4 launches total: k_spmm is launch #4 (ncu capture slot)
    k_comb <<<1, 512>>>(wgcn, bgcn, wout, bout);
    k_build<<<1, 1024>>>(ei, ew);

    size_t gate_smem = sizeof(SmemGate);      // ~95 KB
    cudaFuncSetAttribute(k_gate, cudaFuncAttributeMaxDynamicSharedMemorySize,
                         (int)gate_smem);
    k_gate<<<BB * (NN / NB), dim3(32, 8), gate_smem>>>(x, wg1, bg1, wg2, bg2, out);

    size_t smem_bytes = (size_t)NN * 32 * sizeof(float);   // 128 KB
    cudaFuncSetAttribute(k_spmm, cudaFuncAttributeMaxDynamicSharedMemorySize,
                         (int)smem_bytes);
    k_spmm<<<2 * GG, 1024, smem_bytes>>>(out + OUT1_ELEMS);
}

// round 12
// speedup vs baseline: 1.2149x; 1.2149x over previous
#include <cuda_runtime.h>
#include <cuda_fp16.h>
#include <cstdint>

// ---------------- problem constants ----------------
#define BB   16
#define TT   34
#define TP   32          // T - DIL
#define NN   1000
#define CIN  32
#define DC   32
#define OC   64
#define EE   16000
#define NNZ  (EE + NN)   // edges + self loops = 17000
#define GG   (BB * TP)   // 512 graphs
#define NB   4           // nodes per k_gate block

#define OUT1_ELEMS ((size_t)BB * DC * NN * TP)        // 16,384,000

typedef unsigned long long u64c;

// ---------------- f32x2 packed helpers ----------------
__device__ __forceinline__ u64c fma2(u64c a, u64c b, u64c c) {
    u64c d;
    asm("fma.rn.f32x2 %0, %1, %2, %3;" : "=l"(d) : "l"(a), "l"(b), "l"(c));
    return d;
}
__device__ __forceinline__ u64c add2(u64c a, u64c b) {
    u64c d;
    asm("add.rn.f32x2 %0, %1, %2;" : "=l"(d) : "l"(a), "l"(b));
    return d;
}
__device__ __forceinline__ float f2sum(u64c a) {
    return __int_as_float((int)(a & 0xffffffffULL)) +
           __int_as_float((int)(a >> 32));
}
__device__ __forceinline__ u64c pack2(float lo, float hi) {
    u64c r;
    asm("mov.b64 %0, {%1, %2};" : "=l"(r) : "f"(lo), "f"(hi));
    return r;
}
__device__ __forceinline__ float u64lo(u64c a) { return __int_as_float((int)(a & 0xffffffffULL)); }
__device__ __forceinline__ float u64hi(u64c a) { return __int_as_float((int)(a >> 32)); }
// half2 (as uint) -> packed f32x2
__device__ __forceinline__ u64c h2tof2(unsigned int h) {
    __half2 hv = *(__half2*)&h;
    float2 f = __half22float2(hv);
    u64c r;
    asm("mov.b64 %0, {%1, %2};" : "=l"(r) : "f"(f.x), "f"(f.y));
    return r;
}

// ---------------- device scratch ----------------
__device__ __half g_zh[(size_t)GG * NN * OC];  // 65.5 MB: z = gated @ Wcomb^T (fp16)
__device__ float  g_wcomb[OC * DC];            // Wcomb[o][d] = sum_c wout[o][c] wgcn[c][d]
__device__ float  g_ybias[OC];                 // bgcn @ wout^T + bout
__device__ int    g_off[NN + 1];
__device__ int2   g_csr[NNZ];                  // (src*128 byte offset, f32 val as int)

// ---------------- K_comb: combined weights (propagate/conv commute) --------
__global__ void k_comb(const float* __restrict__ wgcn,
                       const float* __restrict__ wout) {
    __shared__ float sg[CIN * DC];   // wgcn [c][d]
    __shared__ float so[OC * CIN];   // wout [o][c]
    int tid = threadIdx.x;
    for (int f = tid; f < CIN * DC; f += blockDim.x) sg[f] = wgcn[f];
    for (int f = tid; f < OC * CIN; f += blockDim.x) so[f] = wout[f];
    __syncthreads();
    for (int f = tid; f < OC * DC; f += blockDim.x) {
        int o = f >> 5, d = f & 31;
        float s = 0.f;
#pragma unroll
        for (int c = 0; c < CIN; c++) s += so[o * CIN + c] * sg[c * DC + d];
        g_wcomb[f] = s;
    }
}

// ---------------- K_bias: ybias = bgcn @ wout^T + bout ----------------------
__global__ void k_bias(const float* __restrict__ bgcn,
                       const float* __restrict__ wout,
                       const float* __restrict__ bout) {
    int o = threadIdx.x;
    if (o < OC) {
        float s = bout[o];
#pragma unroll
        for (int c = 0; c < CIN; c++) s += bgcn[c] * wout[o * CIN + c];
        g_ybias[o] = s;
    }
}

// ---------------- K_build: fused CSR build (single block, smem atomics) ----
__global__ __launch_bounds__(1024) void k_build(const int* __restrict__ ei,
                                                const float* __restrict__ ew) {
    __shared__ float sdeg[NN];
    __shared__ int   scnt[NN];
    __shared__ int   ssc[1024];
    __shared__ int   scur[NN];
    int tid = threadIdx.x;

    for (int i = tid; i < NN; i += 1024) { sdeg[i] = 0.f; scnt[i] = 0; }
    __syncthreads();

    for (int i = tid; i < NNZ; i += 1024) {
        int d; float w;
        if (i < EE) { d = ei[EE + i]; w = ew[i]; }
        else        { d = i - EE;     w = 1.f;   }
        atomicAdd(&sdeg[d], w);
        atomicAdd(&scnt[d], 1);
    }
    __syncthreads();

    int v = (tid < NN) ? scnt[tid] : 0;
    ssc[tid] = v;
    __syncthreads();
    for (int off = 1; off < 1024; off <<= 1) {
        int tv = (tid >= off) ? ssc[tid - off] : 0;
        __syncthreads();
        ssc[tid] += tv;
        __syncthreads();
    }
    if (tid < NN) {
        int excl = ssc[tid] - v;
        scur[tid] = excl;
        g_off[tid] = excl;
    }
    if (tid == NN - 1) g_off[NN] = ssc[tid];
    __syncthreads();

    for (int i = tid; i < NNZ; i += 1024) {
        int s, d; float w;
        if (i < EE) { s = ei[i]; d = ei[EE + i]; w = ew[i]; }
        else        { s = i - EE; d = s;         w = 1.f;   }
        float degs = sdeg[s], degd = sdeg[d];
        float dis_s = (degs > 0.f) ? rsqrtf(degs) : 0.f;
        float dis_d = (degd > 0.f) ? rsqrtf(degd) : 0.f;
        int p = atomicAdd(&scur[d], 1);
        // fp16 slab row pitch = 64 ch * 2B = 128 B
        g_csr[p] = make_int2(s * 128, __float_as_int(dis_s * w * dis_d));
    }
}

// ---------------- K_gate: fused gated conv + z, NB=4 nodes per block -------
// (R10 structure — the 430us version.) Phase 1: warp wy owns o-quad, t = lane,
// NB-node weight reuse, packed fma2, conflict-free STS.128 of gated. Phase 2:
// thread (o = tid&63, ts = tid>>6) computes z with Wcomb row in regs; z now
// stored as fp16 (STG.16, same count as before, half the bytes).
struct SmemGate {
    float4 xq[NB][8][34];                  // [nb][c4][t]
    float4 w1a[32][8], w1b[32][8];         // [o][c4]
    float4 w2a[32][8], w2b[32][8];
    float4 wcq[8][64];                     // [d4][o] = Wcomb[o][4d4..4d4+3]
    float  gs[NB][32 * 36];                // gated [t][d], pitch 36
};

__global__ __launch_bounds__(256) void k_gate(
    const float* __restrict__ x,
    const float* __restrict__ wg1, const float* __restrict__ bg1,
    const float* __restrict__ wg2, const float* __restrict__ bg2,
    float* __restrict__ out1)
{
    extern __shared__ char smem_raw[];
    SmemGate& S = *(SmemGate*)smem_raw;

    int blk = blockIdx.x;                  // 4000 blocks
    int b  = blk / (NN / NB);
    int n0 = (blk - b * (NN / NB)) * NB;

    int tx = threadIdx.x;                  // 0..31 (t)
    int wy = threadIdx.y;                  // 0..7  (o-quad)
    int tid = wy * 32 + tx;

    // stage gate weights (flat f = o*32+c, 1024 per array)
    for (int f = tid; f < 32 * 32; f += 256) {
        float2 v1 = *(const float2*)(wg1 + f * 2);
        float2 v2 = *(const float2*)(wg2 + f * 2);
        ((float*)S.w1a)[f] = v1.x;
        ((float*)S.w1b)[f] = v1.y;
        ((float*)S.w2a)[f] = v2.x;
        ((float*)S.w2b)[f] = v2.y;
    }
    // stage Wcomb: flat f = (d4*64+o)*4+k  <-  wcomb[o*32 + d4*4 + k]
    for (int f = tid; f < 8 * 64 * 4; f += 256) {
        int k = f & 3, o = (f >> 2) & 63, d4 = f >> 8;
        ((float*)S.wcq)[f] = g_wcomb[o * 32 + d4 * 4 + k];
    }
    // stage x tiles: NB nodes x 34 t x 8 c4
    for (int f = tid; f < NB * 34 * 8; f += 256) {
        int nb = f / (34 * 8);
        int r  = f - nb * (34 * 8);
        int t = r >> 3, c4 = r & 7;
        S.xq[nb][c4][t] =
            *(const float4*)(x + ((size_t)(b * TT + t) * NN + (n0 + nb)) * CIN + c4 * 4);
    }
    __syncthreads();

    // ---- phase 1: gates ----
    {
        float bg1v[4], bg2v[4];
#pragma unroll
        for (int oo = 0; oo < 4; oo++) {
            bg1v[oo] = __ldg(bg1 + 4 * wy + oo);
            bg2v[oo] = __ldg(bg2 + 4 * wy + oo);
        }
        u64c a1[4][NB], a2[4][NB];
#pragma unroll
        for (int oo = 0; oo < 4; oo++)
#pragma unroll
            for (int nb = 0; nb < NB; nb++) { a1[oo][nb] = 0; a2[oo][nb] = 0; }

#pragma unroll
        for (int c4 = 0; c4 < 8; c4++) {
            ulonglong2 xa[NB], xb[NB];
#pragma unroll
            for (int nb = 0; nb < NB; nb++) {
                xa[nb] = *(const ulonglong2*)&S.xq[nb][c4][tx];
                xb[nb] = *(const ulonglong2*)&S.xq[nb][c4][tx + 2];
            }
#pragma unroll
            for (int oo = 0; oo < 4; oo++) {
                int o = 4 * wy + oo;
                ulonglong2 A1 = *(const ulonglong2*)&S.w1a[o][c4];
                ulonglong2 B1 = *(const ulonglong2*)&S.w1b[o][c4];
                ulonglong2 A2 = *(const ulonglong2*)&S.w2a[o][c4];
                ulonglong2 B2 = *(const ulonglong2*)&S.w2b[o][c4];
#pragma unroll
                for (int nb = 0; nb < NB; nb++) {
                    a1[oo][nb] = fma2(xa[nb].x, A1.x, a1[oo][nb]);
                    a1[oo][nb] = fma2(xa[nb].y, A1.y, a1[oo][nb]);
                    a1[oo][nb] = fma2(xb[nb].x, B1.x, a1[oo][nb]);
                    a1[oo][nb] = fma2(xb[nb].y, B1.y, a1[oo][nb]);
                    a2[oo][nb] = fma2(xa[nb].x, A2.x, a2[oo][nb]);
                    a2[oo][nb] = fma2(xa[nb].y, A2.y, a2[oo][nb]);
                    a2[oo][nb] = fma2(xb[nb].x, B2.x, a2[oo][nb]);
                    a2[oo][nb] = fma2(xb[nb].y, B2.y, a2[oo][nb]);
                }
            }
        }

#pragma unroll
        for (int nb = 0; nb < NB; nb++) {
            float4 gq;
#pragma unroll
            for (int oo = 0; oo < 4; oo++) {
                int o = 4 * wy + oo;
                float s1 = f2sum(a1[oo][nb]) + bg1v[oo];
                float s2 = f2sum(a2[oo][nb]) + bg2v[oo];
                float e1 = __expf(2.f * s1);
                float th = 1.f - __fdividef(2.f, e1 + 1.f);    // tanh, inf-safe
                float sg = __fdividef(1.f, 1.f + __expf(-s2)); // sigmoid
                float gated = th * sg;
                out1[((size_t)(b * DC + o) * NN + (n0 + nb)) * TP + tx] = gated;
                (&gq.x)[oo] = gated;
            }
            *(float4*)&S.gs[nb][tx * 36 + 4 * wy] = gq;   // conflict-free STS.128
        }
    }
    __syncthreads();

    // ---- phase 2: z[t][o] = sum_d gated[t][d] * Wcomb[o][d]  (fp16 store) --
    {
        int o  = tid & 63;
        int ts = tid >> 6;          // 0..3
        ulonglong2 wr[8];
#pragma unroll
        for (int d4 = 0; d4 < 8; d4++)
            wr[d4] = *(const ulonglong2*)&S.wcq[d4][o];
#pragma unroll
        for (int nb = 0; nb < NB; nb++) {
            const float* gsn = S.gs[nb];
#pragma unroll
            for (int it = 0; it < 8; it++) {
                int t = ts * 8 + it;
                const ulonglong2* gp = (const ulonglong2*)(gsn + t * 36);
                u64c za = 0, zb = 0;
#pragma unroll
                for (int d4 = 0; d4 < 8; d4++) {
                    ulonglong2 g2 = gp[d4];
                    za = fma2(g2.x, wr[d4].x, za);
                    zb = fma2(g2.y, wr[d4].y, zb);
                }
                g_zh[((size_t)(b * TP + t) * NN + (n0 + nb)) * OC + o] =
                    __float2half(f2sum(za) + f2sum(zb));
            }
        }
    }
}

// ---------------- K_spmm: pure gather over fp16 z, one block per graph -----
// 512 blocks. Full-graph z slab (1000 x 64 half = 128 KB) staged in dynamic
// SMEM (likely L2-resident from k_gate). Warp = 4 subgroups x 8 lanes;
// subgroup walks one row's edge list; lane covers 8 channels (one uint4 =
// 8 halves per edge -> 1 LDS.128 wavefront per subgroup-edge, conflict-free).
// Accumulate fp32 via packed fma2 after half2->f32x2 converts.
__global__ __launch_bounds__(1024, 1) void k_spmm(float* __restrict__ y)
{
    extern __shared__ char z_raw[];           // [N][64] halves, 128 B rows
    int g   = blockIdx.x;
    int tid = threadIdx.x;

    // stage slab (contiguous): 8000 uint4
    {
        const uint4* src = (const uint4*)(g_zh + (size_t)g * NN * OC);
        uint4* dst = (uint4*)z_raw;
        for (int f = tid; f < NN * OC / 8; f += 1024)
            dst[f] = src[f];
    }
    __syncthreads();

    int lane = tid & 31;
    int sub  = (lane >> 3);                   // 0..3 row subgroup
    int l8   = lane & 7;                      // channel octet
    int o0   = l8 * 8;
    int warp = tid >> 5;

    float4 yb0 = *(const float4*)(g_ybias + o0);
    float4 yb1 = *(const float4*)(g_ybias + o0 + 4);
    const char* zb = z_raw + l8 * 16;

    for (int i0 = warp * 4 + sub; i0 < NN + 3; i0 += 128) {
        bool valid = (i0 < NN);
        int r0 = 0, r1 = 0;
        if (valid) { r0 = g_off[i0]; r1 = g_off[i0 + 1]; }

        u64c a0 = pack2(yb0.x, yb0.y);
        u64c a1 = pack2(yb0.z, yb0.w);
        u64c a2 = pack2(yb1.x, yb1.y);
        u64c a3 = pack2(yb1.z, yb1.w);

        int e = r0;
        for (; e + 2 <= r1; e += 2) {
            int2 e0 = __ldg(&g_csr[e]);
            int2 e1 = __ldg(&g_csr[e + 1]);
            uint4 z0 = *(const uint4*)(zb + e0.x);
            uint4 z1 = *(const uint4*)(zb + e1.x);
            float v0f = __int_as_float(e0.y);
            float v1f = __int_as_float(e1.y);
            u64c v0 = pack2(v0f, v0f);
            u64c v1 = pack2(v1f, v1f);
            a0 = fma2(h2tof2(z0.x), v0, a0);
            a1 = fma2(h2tof2(z0.y), v0, a1);
            a2 = fma2(h2tof2(z0.z), v0, a2);
            a3 = fma2(h2tof2(z0.w), v0, a3);
            a0 = fma2(h2tof2(z1.x), v1, a0);
            a1 = fma2(h2tof2(z1.y), v1, a1);
            a2 = fma2(h2tof2(z1.z), v1, a2);
            a3 = fma2(h2tof2(z1.w), v1, a3);
        }
        for (; e < r1; e++) {
            int2 ev = __ldg(&g_csr[e]);
            uint4 zz = *(const uint4*)(zb + ev.x);
            float vf = __int_as_float(ev.y);
            u64c vv = pack2(vf, vf);
            a0 = fma2(h2tof2(zz.x), vv, a0);
            a1 = fma2(h2tof2(zz.y), vv, a1);
            a2 = fma2(h2tof2(zz.z), vv, a2);
            a3 = fma2(h2tof2(zz.w), vv, a3);
        }

        if (valid) {
            float* yo = y + ((size_t)g * NN + i0) * OC + o0;
            float4 r0v, r1v;
            r0v.x = u64lo(a0); r0v.y = u64hi(a0);
            r0v.z = u64lo(a1); r0v.w = u64hi(a1);
            r1v.x = u64lo(a2); r1v.y = u64hi(a2);
            r1v.z = u64lo(a3); r1v.w = u64hi(a3);
            *(float4*)yo       = r0v;
            *(float4*)(yo + 4) = r1v;
        }
    }
}

// ---------------- launcher ----------------
extern "C" void kernel_launch(void* const* d_in, const int* in_sizes, int n_in,
                              void* d_out, int out_size)
{
    const float* x    = (const float*)d_in[0];
    const int*   ei   = (const int*)  d_in[1];
    const float* ew   = (const float*)d_in[2];
    const float* wg1  = (const float*)d_in[3];
    const float* bg1  = (const float*)d_in[4];
    const float* wg2  = (const float*)d_in[5];
    const float* bg2  = (const float*)d_in[6];
    const float* wgcn = (const float*)d_in[7];
    const float* bgcn = (const float*)d_in[8];
    const float* wout = (const float*)d_in[9];
    const float* bout = (const float*)d_in[10];
    float* out = (float*)d_out;

    // 5 launches: k_gate is launch #4 (ncu capture slot)
    k_comb <<<1, 512>>>(wgcn, wout);
    k_bias <<<1, 64>>>(bgcn, wout, bout);
    k_build<<<1, 1024>>>(ei, ew);

    size_t gate_smem = sizeof(SmemGate);      // ~60 KB
    cudaFuncSetAttribute(k_gate, cudaFuncAttributeMaxDynamicSharedMemorySize,
                         (int)gate_smem);
    k_gate<<<BB * (NN / NB), dim3(32, 8), gate_smem>>>(x, wg1, bg1, wg2, bg2, out);

    size_t smem_bytes = (size_t)NN * OC * sizeof(__half);   // 128 KB
    cudaFuncSetAttribute(k_spmm, cudaFuncAttributeMaxDynamicSharedMemorySize,
                         (int)smem_bytes);
    k_spmm<<<GG, 1024, smem_bytes>>>(out + OUT1_ELEMS);
}

// round 13
// speedup vs baseline: 1.3272x; 1.0924x over previous
#include <cuda_runtime.h>
#include <cuda_fp16.h>
#include <cstdint>

// ---------------- problem constants ----------------
#define BB   16
#define TT   34
#define TP   32          // T - DIL
#define NN   1000
#define CIN  32
#define DC   32
#define OC   64
#define EE   16000
#define NNZ  (EE + NN)   // edges + self loops = 17000
#define GG   (BB * TP)   // 512 graphs
#define NB   4           // nodes per k_gate block

#define OUT1_ELEMS ((size_t)BB * DC * NN * TP)        // 16,384,000

typedef unsigned long long u64c;

// ---------------- f32x2 packed helpers ----------------
__device__ __forceinline__ u64c fma2(u64c a, u64c b, u64c c) {
    u64c d;
    asm("fma.rn.f32x2 %0, %1, %2, %3;" : "=l"(d) : "l"(a), "l"(b), "l"(c));
    return d;
}
__device__ __forceinline__ float f2sum(u64c a) {
    return __int_as_float((int)(a & 0xffffffffULL)) +
           __int_as_float((int)(a >> 32));
}
__device__ __forceinline__ u64c pack2(float lo, float hi) {
    u64c r;
    asm("mov.b64 %0, {%1, %2};" : "=l"(r) : "f"(lo), "f"(hi));
    return r;
}
__device__ __forceinline__ float u64lo(u64c a) { return __int_as_float((int)(a & 0xffffffffULL)); }
__device__ __forceinline__ float u64hi(u64c a) { return __int_as_float((int)(a >> 32)); }
// half2 (as uint) -> packed f32x2
__device__ __forceinline__ u64c h2tof2(unsigned int h) {
    __half2 hv = *(__half2*)&h;
    float2 f = __half22float2(hv);
    u64c r;
    asm("mov.b64 %0, {%1, %2};" : "=l"(r) : "f"(f.x), "f"(f.y));
    return r;
}

// ---------------- device scratch ----------------
__device__ __half g_zh[(size_t)GG * NN * OC];  // 65.5 MB: z = gated @ Wcomb^T (fp16)
__device__ float  g_wcomb[OC * DC];            // Wcomb[o][d] = sum_c wout[o][c] wgcn[c][d]
__device__ float  g_ybias[OC];                 // bgcn @ wout^T + bout
__device__ int    g_off[NN + 1];
__device__ int2   g_csr[NNZ];                  // (src*128 byte offset, f32 val as int)

// ---------------- K_comb: combined weights (propagate/conv commute) --------
__global__ void k_comb(const float* __restrict__ wgcn,
                       const float* __restrict__ wout) {
    __shared__ float sg[CIN * DC];   // wgcn [c][d]
    __shared__ float so[OC * CIN];   // wout [o][c]
    int tid = threadIdx.x;
    for (int f = tid; f < CIN * DC; f += blockDim.x) sg[f] = wgcn[f];
    for (int f = tid; f < OC * CIN; f += blockDim.x) so[f] = wout[f];
    __syncthreads();
    for (int f = tid; f < OC * DC; f += blockDim.x) {
        int o = f >> 5, d = f & 31;
        float s = 0.f;
#pragma unroll
        for (int c = 0; c < CIN; c++) s += so[o * CIN + c] * sg[c * DC + d];
        g_wcomb[f] = s;
    }
}

// ---------------- K_bias: ybias = bgcn @ wout^T + bout ----------------------
__global__ void k_bias(const float* __restrict__ bgcn,
                       const float* __restrict__ wout,
                       const float* __restrict__ bout) {
    int o = threadIdx.x;
    if (o < OC) {
        float s = bout[o];
#pragma unroll
        for (int c = 0; c < CIN; c++) s += bgcn[c] * wout[o * CIN + c];
        g_ybias[o] = s;
    }
}

// ---------------- K_build: fused CSR build (single block, smem atomics) ----
__global__ __launch_bounds__(1024) void k_build(const int* __restrict__ ei,
                                                const float* __restrict__ ew) {
    __shared__ float sdeg[NN];
    __shared__ int   scnt[NN];
    __shared__ int   ssc[1024];
    __shared__ int   scur[NN];
    int tid = threadIdx.x;

    for (int i = tid; i < NN; i += 1024) { sdeg[i] = 0.f; scnt[i] = 0; }
    __syncthreads();

    for (int i = tid; i < NNZ; i += 1024) {
        int d; float w;
        if (i < EE) { d = ei[EE + i]; w = ew[i]; }
        else        { d = i - EE;     w = 1.f;   }
        atomicAdd(&sdeg[d], w);
        atomicAdd(&scnt[d], 1);
    }
    __syncthreads();

    int v = (tid < NN) ? scnt[tid] : 0;
    ssc[tid] = v;
    __syncthreads();
    for (int off = 1; off < 1024; off <<= 1) {
        int tv = (tid >= off) ? ssc[tid - off] : 0;
        __syncthreads();
        ssc[tid] += tv;
        __syncthreads();
    }
    if (tid < NN) {
        int excl = ssc[tid] - v;
        scur[tid] = excl;
        g_off[tid] = excl;
    }
    if (tid == NN - 1) g_off[NN] = ssc[tid];
    __syncthreads();

    for (int i = tid; i < NNZ; i += 1024) {
        int s, d; float w;
        if (i < EE) { s = ei[i]; d = ei[EE + i]; w = ew[i]; }
        else        { s = i - EE; d = s;         w = 1.f;   }
        float degs = sdeg[s], degd = sdeg[d];
        float dis_s = (degs > 0.f) ? rsqrtf(degs) : 0.f;
        float dis_d = (degd > 0.f) ? rsqrtf(degd) : 0.f;
        int p = atomicAdd(&scur[d], 1);
        // fp16 slab row pitch = 64 ch * 2B = 128 B
        g_csr[p] = make_int2(s * 128, __float_as_int(dis_s * w * dis_d));
    }
}

// ---------------- K_gate: fused gated conv + z, NB=4 nodes per block -------
// Phase 1: warp wy owns o-quad, t = lane, NB-node weight reuse, packed fma2.
// gated written to smem as HALF2 pairs (STS.64, 2-way-optimal banking) AND to
// out1 in exact fp32. Phase 2: thread (o = tid&63, ts = tid>>6) reads gs as
// LDS.64 broadcasts (half the wavefronts of LDS.128), converts half2->f32x2,
// fma2 against the register-cached Wcomb row; z stored fp16.
// __launch_bounds__(256,2): cap 128 regs -> 2 blocks/SM (R12 ran 132 regs ->
// 1 block/SM -> occ 12.5%, latency-bound).
#define GSP 18   // gs pitch in half2 units (36 halves = 72B per t-row)
struct SmemGate {
    float4 xq[NB][8][34];                  // [nb][c4][t]
    float4 w1a[32][8], w1b[32][8];         // [o][c4]
    float4 w2a[32][8], w2b[32][8];
    float4 wcq[8][64];                     // [d4][o] = Wcomb[o][4d4..4d4+3]
    unsigned int gs[NB][32 * GSP];         // gated [t][d-pairs] as half2
};

__global__ __launch_bounds__(256, 2) void k_gate(
    const float* __restrict__ x,
    const float* __restrict__ wg1, const float* __restrict__ bg1,
    const float* __restrict__ wg2, const float* __restrict__ bg2,
    float* __restrict__ out1)
{
    extern __shared__ char smem_raw[];
    SmemGate& S = *(SmemGate*)smem_raw;

    int blk = blockIdx.x;                  // 4000 blocks
    int b  = blk / (NN / NB);
    int n0 = (blk - b * (NN / NB)) * NB;

    int tx = threadIdx.x;                  // 0..31 (t)
    int wy = threadIdx.y;                  // 0..7  (o-quad)
    int tid = wy * 32 + tx;

    // stage gate weights (flat f = o*32+c, 1024 per array)
    for (int f = tid; f < 32 * 32; f += 256) {
        float2 v1 = *(const float2*)(wg1 + f * 2);
        float2 v2 = *(const float2*)(wg2 + f * 2);
        ((float*)S.w1a)[f] = v1.x;
        ((float*)S.w1b)[f] = v1.y;
        ((float*)S.w2a)[f] = v2.x;
        ((float*)S.w2b)[f] = v2.y;
    }
    // stage Wcomb: flat f = (d4*64+o)*4+k  <-  wcomb[o*32 + d4*4 + k]
    for (int f = tid; f < 8 * 64 * 4; f += 256) {
        int k = f & 3, o = (f >> 2) & 63, d4 = f >> 8;
        ((float*)S.wcq)[f] = g_wcomb[o * 32 + d4 * 4 + k];
    }
    // stage x tiles: NB nodes x 34 t x 8 c4
    for (int f = tid; f < NB * 34 * 8; f += 256) {
        int nb = f / (34 * 8);
        int r  = f - nb * (34 * 8);
        int t = r >> 3, c4 = r & 7;
        S.xq[nb][c4][t] =
            *(const float4*)(x + ((size_t)(b * TT + t) * NN + (n0 + nb)) * CIN + c4 * 4);
    }
    __syncthreads();

    // ---- phase 1: gates ----
    {
        float bg1v[4], bg2v[4];
#pragma unroll
        for (int oo = 0; oo < 4; oo++) {
            bg1v[oo] = __ldg(bg1 + 4 * wy + oo);
            bg2v[oo] = __ldg(bg2 + 4 * wy + oo);
        }
        u64c a1[4][NB], a2[4][NB];
#pragma unroll
        for (int oo = 0; oo < 4; oo++)
#pragma unroll
            for (int nb = 0; nb < NB; nb++) { a1[oo][nb] = 0; a2[oo][nb] = 0; }

#pragma unroll
        for (int c4 = 0; c4 < 8; c4++) {
            ulonglong2 xa[NB], xb[NB];
#pragma unroll
            for (int nb = 0; nb < NB; nb++) {
                xa[nb] = *(const ulonglong2*)&S.xq[nb][c4][tx];
                xb[nb] = *(const ulonglong2*)&S.xq[nb][c4][tx + 2];
            }
#pragma unroll
            for (int oo = 0; oo < 4; oo++) {
                int o = 4 * wy + oo;
                ulonglong2 A1 = *(const ulonglong2*)&S.w1a[o][c4];
                ulonglong2 B1 = *(const ulonglong2*)&S.w1b[o][c4];
                ulonglong2 A2 = *(const ulonglong2*)&S.w2a[o][c4];
                ulonglong2 B2 = *(const ulonglong2*)&S.w2b[o][c4];
#pragma unroll
                for (int nb = 0; nb < NB; nb++) {
                    a1[oo][nb] = fma2(xa[nb].x, A1.x, a1[oo][nb]);
                    a1[oo][nb] = fma2(xa[nb].y, A1.y, a1[oo][nb]);
                    a1[oo][nb] = fma2(xb[nb].x, B1.x, a1[oo][nb]);
                    a1[oo][nb] = fma2(xb[nb].y, B1.y, a1[oo][nb]);
                    a2[oo][nb] = fma2(xa[nb].x, A2.x, a2[oo][nb]);
                    a2[oo][nb] = fma2(xa[nb].y, A2.y, a2[oo][nb]);
                    a2[oo][nb] = fma2(xb[nb].x, B2.x, a2[oo][nb]);
                    a2[oo][nb] = fma2(xb[nb].y, B2.y, a2[oo][nb]);
                }
            }
        }

#pragma unroll
        for (int nb = 0; nb < NB; nb++) {
            float4 gq;
#pragma unroll
            for (int oo = 0; oo < 4; oo++) {
                int o = 4 * wy + oo;
                float s1 = f2sum(a1[oo][nb]) + bg1v[oo];
                float s2 = f2sum(a2[oo][nb]) + bg2v[oo];
                float e1 = __expf(2.f * s1);
                float th = 1.f - __fdividef(2.f, e1 + 1.f);    // tanh, inf-safe
                float sg = __fdividef(1.f, 1.f + __expf(-s2)); // sigmoid
                float gated = th * sg;
                out1[((size_t)(b * DC + o) * NN + (n0 + nb)) * TP + tx] = gated;
                (&gq.x)[oo] = gated;
            }
            // fp16 pack: one STS.64 of 2 half2 (2-way-optimal banking, pitch 36 halves)
            __half2 h0 = __floats2half2_rn(gq.x, gq.y);
            __half2 h1 = __floats2half2_rn(gq.z, gq.w);
            uint2 hp;
            hp.x = *(unsigned int*)&h0;
            hp.y = *(unsigned int*)&h1;
            *(uint2*)&S.gs[nb][tx * GSP + wy * 2] = hp;
        }
    }
    __syncthreads();

    // ---- phase 2: z[t][o] = sum_d gated[t][d] * Wcomb[o][d]  (fp16 in/out) --
    {
        int o  = tid & 63;
        int ts = tid >> 6;          // 0..3
        ulonglong2 wr[8];
#pragma unroll
        for (int d4 = 0; d4 < 8; d4++)
            wr[d4] = *(const ulonglong2*)&S.wcq[d4][o];
#pragma unroll
        for (int nb = 0; nb < NB; nb++) {
            const unsigned int* gsn = S.gs[nb];
#pragma unroll
            for (int it = 0; it < 8; it++) {
                int t = ts * 8 + it;
                u64c za = 0, zb = 0;
#pragma unroll
                for (int d4 = 0; d4 < 8; d4++) {
                    uint2 gg = *(const uint2*)&gsn[t * GSP + d4 * 2];  // LDS.64 bcast
                    za = fma2(h2tof2(gg.x), wr[d4].x, za);
                    zb = fma2(h2tof2(gg.y), wr[d4].y, zb);
                }
                g_zh[((size_t)(b * TP + t) * NN + (n0 + nb)) * OC + o] =
                    __float2half(f2sum(za) + f2sum(zb));
            }
        }
    }
}

// ---------------- K_spmm: pure gather over fp16 z, one block per graph -----
// 512 blocks. Full-graph z slab (1000 x 64 half = 128 KB) staged in dynamic
// SMEM. Warp = 4 subgroups x 8 lanes; subgroup walks one row's edge list;
// lane covers 8 channels (one uint4 = 8 halves per edge). fp32 accumulation
// via packed fma2 after half2->f32x2 converts.
__global__ __launch_bounds__(1024, 1) void k_spmm(float* __restrict__ y)
{
    extern __shared__ char z_raw[];           // [N][64] halves, 128 B rows
    int g   = blockIdx.x;
    int tid = threadIdx.x;

    {
        const uint4* src = (const uint4*)(g_zh + (size_t)g * NN * OC);
        uint4* dst = (uint4*)z_raw;
        for (int f = tid; f < NN * OC / 8; f += 1024)
            dst[f] = src[f];
    }
    __syncthreads();

    int lane = tid & 31;
    int sub  = (lane >> 3);                   // 0..3 row subgroup
    int l8   = lane & 7;                      // channel octet
    int o0   = l8 * 8;
    int warp = tid >> 5;

    float4 yb0 = *(const float4*)(g_ybias + o0);
    float4 yb1 = *(const float4*)(g_ybias + o0 + 4);
    const char* zb = z_raw + l8 * 16;

    for (int i0 = warp * 4 + sub; i0 < NN + 3; i0 += 128) {
        bool valid = (i0 < NN);
        int r0 = 0, r1 = 0;
        if (valid) { r0 = g_off[i0]; r1 = g_off[i0 + 1]; }

        u64c a0 = pack2(yb0.x, yb0.y);
        u64c a1 = pack2(yb0.z, yb0.w);
        u64c a2 = pack2(yb1.x, yb1.y);
        u64c a3 = pack2(yb1.z, yb1.w);

        int e = r0;
        for (; e + 2 <= r1; e += 2) {
            int2 e0 = __ldg(&g_csr[e]);
            int2 e1 = __ldg(&g_csr[e + 1]);
            uint4 z0 = *(const uint4*)(zb + e0.x);
            uint4 z1 = *(const uint4*)(zb + e1.x);
            float v0f = __int_as_float(e0.y);
            float v1f = __int_as_float(e1.y);
            u64c v0 = pack2(v0f, v0f);
            u64c v1 = pack2(v1f, v1f);
            a0 = fma2(h2tof2(z0.x), v0, a0);
            a1 = fma2(h2tof2(z0.y), v0, a1);
            a2 = fma2(h2tof2(z0.z), v0, a2);
            a3 = fma2(h2tof2(z0.w), v0, a3);
            a0 = fma2(h2tof2(z1.x), v1, a0);
            a1 = fma2(h2tof2(z1.y), v1, a1);
            a2 = fma2(h2tof2(z1.z), v1, a2);
            a3 = fma2(h2tof2(z1.w), v1, a3);
        }
        for (; e < r1; e++) {
            int2 ev = __ldg(&g_csr[e]);
            uint4 zz = *(const uint4*)(zb + ev.x);
            float vf = __int_as_float(ev.y);
            u64c vv = pack2(vf, vf);
            a0 = fma2(h2tof2(zz.x), vv, a0);
            a1 = fma2(h2tof2(zz.y), vv, a1);
            a2 = fma2(h2tof2(zz.z), vv, a2);
            a3 = fma2(h2tof2(zz.w), vv, a3);
        }

        if (valid) {
            float* yo = y + ((size_t)g * NN + i0) * OC + o0;
            float4 r0v, r1v;
            r0v.x = u64lo(a0); r0v.y = u64hi(a0);
            r0v.z = u64lo(a1); r0v.w = u64hi(a1);
            r1v.x = u64lo(a2); r1v.y = u64hi(a2);
            r1v.z = u64lo(a3); r1v.w = u64hi(a3);
            *(float4*)yo       = r0v;
            *(float4*)(yo + 4) = r1v;
        }
    }
}

// ---------------- launcher ----------------
extern "C" void kernel_launch(void* const* d_in, const int* in_sizes, int n_in,
                              void* d_out, int out_size)
{
    const float* x    = (const float*)d_in[0];
    const int*   ei   = (const int*)  d_in[1];
    const float* ew   = (const float*)d_in[2];
    const float* wg1  = (const float*)d_in[3];
    const float* bg1  = (const float*)d_in[4];
    const float* wg2  = (const float*)d_in[5];
    const float* bg2  = (const float*)d_in[6];
    const float* wgcn = (const float*)d_in[7];
    const float* bgcn = (const float*)d_in[8];
    const float* wout = (const float*)d_in[9];
    const float* bout = (const float*)d_in[10];
    float* out = (float*)d_out;

    // 5 launches: k_gate is launch #4 (ncu capture slot)
    k_comb <<<1, 512>>>(wgcn, wout);
    k_bias <<<1, 64>>>(bgcn, wout, bout);
    k_build<<<1, 1024>>>(ei, ew);

    size_t gate_smem = sizeof(SmemGate);      // ~51 KB (2 blocks/SM fits)
    cudaFuncSetAttribute(k_gate, cudaFuncAttributeMaxDynamicSharedMemorySize,
                         (int)gate_smem);
    k_gate<<<BB * (NN / NB), dim3(32, 8), gate_smem>>>(x, wg1, bg1, wg2, bg2, out);

    size_t smem_bytes = (size_t)NN * OC * sizeof(__half);   // 128 KB
    cudaFuncSetAttribute(k_spmm, cudaFuncAttributeMaxDynamicSharedMemorySize,
                         (int)smem_bytes);
    k_spmm<<<GG, 1024, smem_bytes>>>(out + OUT1_ELEMS);
}